// round 11
// baseline (speedup 1.0000x reference)
#include <cuda_runtime.h>
#include <cuda_bf16.h>
#include <math.h>
#include <stdint.h>

// ---------------- problem constants ----------------
#define BB   2
#define SS   2048
#define DIM_ 2048
#define HH   16
#define DH_  128
#define LAT_ 512
#define DR_  64
#define NQ_  (HH * (DH_ + DR_))   // 3072
#define CS_  3712                 // combined q||kr||pad||ckv stride (29 tiles)
#define NKV_ (HH * 2 * DH_)       // 4096
#define NO_  (HH * DH_)           // 2048
#define ROWS (BB * SS)            // 4096

// ---------------- scratch (device globals; no allocation allowed) ----------
__device__ __align__(16) __nv_bfloat16 g_xh   [ROWS * (size_t)DIM_];
__device__ __align__(16) __nv_bfloat16 g_xl   [ROWS * (size_t)DIM_];
__device__ __align__(16) __nv_bfloat16 g_ph   [ROWS * (size_t)CS_];   // q|kr|pad|ckv hi
__device__ __align__(16) __nv_bfloat16 g_pl   [ROWS * (size_t)CS_];   // lo
__device__ __align__(16) __nv_bfloat16 g_kvh  [ROWS * (size_t)NKV_];
__device__ __align__(16) __nv_bfloat16 g_kvl  [ROWS * (size_t)NKV_];
__device__ __align__(16) __nv_bfloat16 g_atth [ROWS * (size_t)NO_];
__device__ __align__(16) __nv_bfloat16 g_attl [ROWS * (size_t)NO_];
// combined weight [Wq*scale | Wkr | 0 | Wdkv] transposed: CS_ x DIM_
__device__ __align__(16) __nv_bfloat16 g_wch  [CS_  * (size_t)DIM_];
__device__ __align__(16) __nv_bfloat16 g_wcl  [CS_  * (size_t)DIM_];
__device__ __align__(16) __nv_bfloat16 g_wuh  [NKV_ * (size_t)LAT_];
__device__ __align__(16) __nv_bfloat16 g_wul  [NKV_ * (size_t)LAT_];
__device__ __align__(16) __nv_bfloat16 g_woh  [DIM_ * (size_t)NO_];
__device__ __align__(16) __nv_bfloat16 g_wol  [DIM_ * (size_t)NO_];

// ---------------- PTX helpers (arch-portable) ----------
__device__ __forceinline__ uint32_t smem_u32(const void* p) {
    uint32_t a;
    asm("{ .reg .u64 t; cvta.to.shared.u64 t, %1; cvt.u32.u64 %0, t; }"
        : "=r"(a) : "l"(p));
    return a;
}
__device__ __forceinline__ void cpa16(uint32_t dst, const void* src) {
    asm volatile("cp.async.cg.shared.global [%0], [%1], 16;"
                 :: "r"(dst), "l"(src) : "memory");
}
__device__ __forceinline__ void cpa_commit() {
    asm volatile("cp.async.commit_group;" ::: "memory");
}
__device__ __forceinline__ void cpa_wait0() {
    asm volatile("cp.async.wait_group 0;" ::: "memory");
}
__device__ __forceinline__ void cpa_wait1() {
    asm volatile("cp.async.wait_group 1;" ::: "memory");
}
__device__ __forceinline__ void ldmx4(uint32_t* r, uint32_t addr) {
    asm volatile("ldmatrix.sync.aligned.m8n8.x4.shared.b16 {%0,%1,%2,%3}, [%4];"
        : "=r"(r[0]), "=r"(r[1]), "=r"(r[2]), "=r"(r[3]) : "r"(addr));
}
__device__ __forceinline__ void ldmx4t(uint32_t* r, uint32_t addr) {
    asm volatile("ldmatrix.sync.aligned.m8n8.x4.trans.shared.b16 {%0,%1,%2,%3}, [%4];"
        : "=r"(r[0]), "=r"(r[1]), "=r"(r[2]), "=r"(r[3]) : "r"(addr));
}
__device__ __forceinline__ void mma16816(float* d, const uint32_t* a, const uint32_t* b) {
    asm volatile(
        "mma.sync.aligned.m16n8k16.row.col.f32.bf16.bf16.f32 "
        "{%0,%1,%2,%3}, {%4,%5,%6,%7}, {%8,%9}, {%0,%1,%2,%3};"
        : "+f"(d[0]), "+f"(d[1]), "+f"(d[2]), "+f"(d[3])
        : "r"(a[0]), "r"(a[1]), "r"(a[2]), "r"(a[3]), "r"(b[0]), "r"(b[1]));
}

// ---------------- elementwise split (x only) ----------------
__global__ __launch_bounds__(256) void split_k(
    const float* __restrict__ A, __nv_bfloat16* __restrict__ h,
    __nv_bfloat16* __restrict__ l, int n4)
{
    int i = blockIdx.x * 256 + threadIdx.x;
    if (i >= n4) return;
    float4 v = *(const float4*)(A + (size_t)i * 4);
    __nv_bfloat16 hx = __float2bfloat16(v.x), hy = __float2bfloat16(v.y);
    __nv_bfloat16 hz = __float2bfloat16(v.z), hw = __float2bfloat16(v.w);
    __nv_bfloat162* hp = (__nv_bfloat162*)(h + (size_t)i * 4);
    hp[0] = __nv_bfloat162(hx, hy);
    hp[1] = __nv_bfloat162(hz, hw);
    __nv_bfloat162* lp = (__nv_bfloat162*)(l + (size_t)i * 4);
    lp[0] = __nv_bfloat162(__float2bfloat16(v.x - __bfloat162float(hx)),
                           __float2bfloat16(v.y - __bfloat162float(hy)));
    lp[1] = __nv_bfloat162(__float2bfloat16(v.z - __bfloat162float(hz)),
                           __float2bfloat16(v.w - __bfloat162float(hw)));
}

// ---------------- transpose + split weights: T[n][k] = alpha*B[k][n] -------
__global__ __launch_bounds__(256) void tsplitw_k(
    const float* __restrict__ B, __nv_bfloat16* __restrict__ Th,
    __nv_bfloat16* __restrict__ Tl, int K, int N, float alpha)
{
    __shared__ float tile[32][33];
    const int tx = threadIdx.x & 31, ty = threadIdx.x >> 5;
    const int n0 = blockIdx.x * 32, k0 = blockIdx.y * 32;
#pragma unroll
    for (int i = 0; i < 32; i += 8)
        tile[ty + i][tx] = B[(size_t)(k0 + ty + i) * N + n0 + tx];
    __syncthreads();
#pragma unroll
    for (int i = 0; i < 32; i += 8) {
        float v = alpha * tile[tx][ty + i];
        __nv_bfloat16 h = __float2bfloat16(v);
        size_t o = (size_t)(n0 + ty + i) * K + k0 + tx;
        Th[o] = h;
        Tl[o] = __float2bfloat16(v - __bfloat162float(h));
    }
}

// ---------------- build combined weight [Wq*scale | Wkr | 0 | Wdkv]^T -----
__global__ __launch_bounds__(256) void buildwc_k(
    const float* __restrict__ Wq, const float* __restrict__ Wkr,
    const float* __restrict__ Wdkv, __nv_bfloat16* __restrict__ Th,
    __nv_bfloat16* __restrict__ Tl, float scale)
{
    __shared__ float tile[32][33];
    const int tx = threadIdx.x & 31, ty = threadIdx.x >> 5;
    const int n0 = blockIdx.x * 32, k0 = blockIdx.y * 32;

    const float* src; int Nsrc, nc; float alpha;
    if (n0 < 3072)      { src = Wq;   Nsrc = NQ_;  nc = n0;        alpha = scale; }
    else if (n0 < 3136) { src = Wkr;  Nsrc = DR_;  nc = n0 - 3072; alpha = 1.0f; }
    else if (n0 < 3200) { src = 0;    Nsrc = 0;    nc = 0;         alpha = 0.0f; }
    else                { src = Wdkv; Nsrc = LAT_; nc = n0 - 3200; alpha = 1.0f; }

    if (src) {
#pragma unroll
        for (int i = 0; i < 32; i += 8)
            tile[ty + i][tx] = src[(size_t)(k0 + ty + i) * Nsrc + nc + tx];
    } else {
#pragma unroll
        for (int i = 0; i < 32; i += 8)
            tile[ty + i][tx] = 0.f;
    }
    __syncthreads();
#pragma unroll
    for (int i = 0; i < 32; i += 8) {
        float v = alpha * tile[tx][ty + i];
        __nv_bfloat16 h = __float2bfloat16(v);
        size_t o = (size_t)(n0 + ty + i) * DIM_ + k0 + tx;
        Th[o] = h;
        Tl[o] = __float2bfloat16(v - __bfloat162float(h));
    }
}

// ---------------- bf16 split-2 HMMA GEMM, 3-stage, 2 CTAs/SM ---------------
// A: [M,K] bf16 hi/lo with row stride lda; B: [N,K] hi/lo (stride K).
#define STG_A 8192
#define STG   32768
#define GEMM_SMEM (3 * STG)

__global__ __launch_bounds__(256, 2) void gemm_mma(
    const __nv_bfloat16* __restrict__ Ah, const __nv_bfloat16* __restrict__ Al,
    const __nv_bfloat16* __restrict__ Bh, const __nv_bfloat16* __restrict__ Bl,
    float* __restrict__ C, __nv_bfloat16* __restrict__ Ch,
    __nv_bfloat16* __restrict__ Cl, int M, int N, int K, int lda, int out_hl)
{
    extern __shared__ char smc[];
    const uint32_t sb = smem_u32(smc);
    const int t = threadIdx.x, wid = t >> 5, lane = t & 31;
    const int m0 = blockIdx.y * 128, n0 = blockIdx.x * 128;
    const int wr = (wid & 3) * 32, wc = (wid >> 2) * 64;

    float acc[2][8][4];
#pragma unroll
    for (int a = 0; a < 2; a++)
#pragma unroll
        for (int b = 0; b < 8; b++)
#pragma unroll
            for (int c = 0; c < 4; c++) acc[a][b][c] = 0.f;

    const int nk = K >> 5;

    auto load_stage = [&](int kc, int s) {
        const uint32_t base = sb + s * STG;
#pragma unroll
        for (int i = 0; i < 2; i++) {
            const int idx = t + i * 256;
            const int r = idx >> 2, c = idx & 3;
            const uint32_t sw = (uint32_t)(r * 64 + ((c ^ ((r >> 1) & 3)) * 16));
            const size_t ga = (size_t)(m0 + r) * lda + kc * 32 + c * 8;
            const size_t gb = (size_t)(n0 + r) * K + kc * 32 + c * 8;
            cpa16(base + sw,             Ah + ga);
            cpa16(base + STG_A + sw,     Al + ga);
            cpa16(base + 2 * STG_A + sw, Bh + gb);
            cpa16(base + 3 * STG_A + sw, Bl + gb);
        }
        cpa_commit();
    };

    // 3 stages, prefetch distance 2, one barrier per iteration.
    load_stage(0, 0);
    load_stage(1, 1);

    for (int kc = 0; kc < nk; kc++) {
        const int s = kc % 3;
        cpa_wait1();          // load(kc) resident (<=1 group pending)
        __syncthreads();      // all warps done with the stage being refilled
        if (kc + 2 < nk) load_stage(kc + 2, (kc + 2) % 3);
        else cpa_commit();    // keep group accounting aligned
        const uint32_t base = sb + s * STG;

#pragma unroll
        for (int ks = 0; ks < 2; ks++) {
            uint32_t ah[2][4], al[2][4];
#pragma unroll
            for (int mi = 0; mi < 2; mi++) {
                const int r = wr + mi * 16 + (lane & 15);
                const int ch = ks * 2 + (lane >> 4);
                const uint32_t ad = base + r * 64 + ((ch ^ ((r >> 1) & 3)) * 16);
                ldmx4(ah[mi], ad);
                ldmx4(al[mi], ad + STG_A);
            }
#pragma unroll
            for (int p = 0; p < 4; p++) {
                const int r = wc + p * 16 + (lane & 7) + ((lane >> 4) << 3);
                const int ch = ks * 2 + ((lane >> 3) & 1);
                const uint32_t bd = base + 2 * STG_A + r * 64 + ((ch ^ ((r >> 1) & 3)) * 16);
                uint32_t bh[4], bl[4];
                ldmx4(bh, bd);
                ldmx4(bl, bd + STG_A);
#pragma unroll
                for (int hh = 0; hh < 2; hh++) {
#pragma unroll
                    for (int mi = 0; mi < 2; mi++) {
                        float* d = acc[mi][p * 2 + hh];
                        mma16816(d, ah[mi], bh + hh * 2);
                        mma16816(d, ah[mi], bl + hh * 2);
                        mma16816(d, al[mi], bh + hh * 2);
                    }
                }
            }
        }
    }

    // epilogue (C row stride == N)
#pragma unroll
    for (int mi = 0; mi < 2; mi++) {
#pragma unroll
        for (int ni = 0; ni < 8; ni++) {
            const int r0 = m0 + wr + mi * 16 + (lane >> 2);
            const int c0 = n0 + wc + ni * 8 + (lane & 3) * 2;
            if (out_hl) {
#pragma unroll
                for (int half = 0; half < 2; half++) {
                    const size_t o = (size_t)(r0 + half * 8) * N + c0;
                    const float v0 = acc[mi][ni][half * 2 + 0];
                    const float v1 = acc[mi][ni][half * 2 + 1];
                    __nv_bfloat162 hv = __floats2bfloat162_rn(v0, v1);
                    *(__nv_bfloat162*)(Ch + o) = hv;
                    *(__nv_bfloat162*)(Cl + o) = __floats2bfloat162_rn(
                        v0 - __bfloat162float(hv.x), v1 - __bfloat162float(hv.y));
                }
            } else {
                float2 v0, v1;
                v0.x = acc[mi][ni][0]; v0.y = acc[mi][ni][1];
                v1.x = acc[mi][ni][2]; v1.y = acc[mi][ni][3];
                *(float2*)&C[(size_t)r0 * N + c0]       = v0;
                *(float2*)&C[(size_t)(r0 + 8) * N + c0] = v1;
            }
        }
    }
}

// ---------------- RoPE in hi/lo domain (q rope blocks + kr block) ---------
__global__ void rope_hl(__nv_bfloat16* __restrict__ h, __nv_bfloat16* __restrict__ l)
{
    int idx = blockIdx.x * blockDim.x + threadIdx.x;   // ROWS*17*32
    if (idx >= ROWS * 17 * 32) return;
    int i   = idx & 31;
    int u   = (idx >> 5) % 17;
    int row = (idx >> 5) / 17;
    int pos = row & (SS - 1);
    float inv = powf(10000.0f, -(float)i / 32.0f);
    float ang = (float)pos * inv;
    float s, c; sincosf(ang, &s, &c);
    size_t base = (size_t)row * CS_ + (u < 16 ? u * 192 + 128 : 3072);
    float x1 = __bfloat162float(h[base + i])      + __bfloat162float(l[base + i]);
    float x2 = __bfloat162float(h[base + i + 32]) + __bfloat162float(l[base + i + 32]);
    float r1 = x1 * c - x2 * s;
    float r2 = x2 * c + x1 * s;
    __nv_bfloat16 h1 = __float2bfloat16(r1), h2 = __float2bfloat16(r2);
    h[base + i]      = h1;
    l[base + i]      = __float2bfloat16(r1 - __bfloat162float(h1));
    h[base + i + 32] = h2;
    l[base + i + 32] = __float2bfloat16(r2 - __bfloat162float(h2));
}

// ---------------- flash attention, split-2 bf16 HMMA ----------------------
// Q fragments hoisted into registers (loaded once, reused across k-tiles).
#define ASTR_ 384
#define VSTR_ 256
#define OQH 0
#define OQL 49152
#define OKH 98304
#define OKL 122880
#define OVH 147456
#define OVL 163840
#define ATT_SMEM 180224

__global__ __launch_bounds__(256, 1) void attn_mma(
    const __nv_bfloat16* __restrict__ qh,  const __nv_bfloat16* __restrict__ ql,
    const __nv_bfloat16* __restrict__ kvh, const __nv_bfloat16* __restrict__ kvl,
    __nv_bfloat16* __restrict__ atth, __nv_bfloat16* __restrict__ attl)
{
    extern __shared__ char smc[];
    const uint32_t sb = smem_u32(smc);
    const int t = threadIdx.x, w = t >> 5, lane = t & 31;
    const int qt = gridDim.x - 1 - blockIdx.x;   // heavy tiles first
    const int h = blockIdx.y, b = blockIdx.z;
    const int q0 = qt * 128;
    const int rowg0 = b * SS + q0;
    const int g = lane >> 2, tq = lane & 3;
    const int qr0 = q0 + w * 16 + g;

    auto loadK = [&](int kt) {
        const int k0 = kt * 64;
#pragma unroll
        for (int it = 0; it < 6; it++) {
            const int idx = t + it * 256;        // 64*24
            const int r = idx / 24, c = idx % 24;
            const uint32_t dst = sb + r * ASTR_ + ((c ^ (r & 7)) * 16);
            const size_t rg = (size_t)(b * SS + k0 + r);
            if (c < 16) {
                const size_t go = rg * NKV_ + h * 256 + c * 8;
                cpa16(dst + OKH, kvh + go);
                cpa16(dst + OKL, kvl + go);
            } else {
                const size_t go = rg * CS_ + 3072 + (c - 16) * 8;
                cpa16(dst + OKH, qh + go);
                cpa16(dst + OKL, ql + go);
            }
        }
        cpa_commit();
    };
    auto loadV = [&](int kt) {
        const int k0 = kt * 64;
#pragma unroll
        for (int it = 0; it < 4; it++) {
            const int idx = t + it * 256;        // 64*16
            const int r = idx >> 4, c = idx & 15;
            const uint32_t dst = sb + r * VSTR_ + ((c ^ (r & 7)) * 16);
            const size_t go = (size_t)(b * SS + k0 + r) * NKV_ + h * 256 + 128 + c * 8;
            cpa16(dst + OVH, kvh + go);
            cpa16(dst + OVL, kvl + go);
        }
        cpa_commit();
    };

    // ---- prologue: Q tile + K(0) ----
#pragma unroll
    for (int it = 0; it < 12; it++) {
        const int idx = t + it * 256;            // 128*24
        const int r = idx / 24, c = idx % 24;
        const uint32_t dst = sb + r * ASTR_ + ((c ^ (r & 7)) * 16);
        const size_t go = (size_t)(rowg0 + r) * CS_ + h * 192 + c * 8;
        cpa16(dst + OQH, qh + go);
        cpa16(dst + OQL, ql + go);
    }
    cpa_commit();
    loadK(0);

    float m0 = -1e30f, m1 = -1e30f, l0 = 0.f, l1 = 0.f;
    float oacc[16][4];
#pragma unroll
    for (int i = 0; i < 16; i++)
#pragma unroll
        for (int j = 0; j < 4; j++) oacc[i][j] = 0.f;

    // hoisted Q fragments (96 regs; attention has register headroom at 1 CTA/SM)
    uint32_t qfh[12][4], qfl[12][4];

    const int nkt = 2 * qt + 2;
    const int wkmax = q0 + w * 16 + 15;

    for (int kt = 0; kt < nkt; kt++) {
        const int k0 = kt * 64;
        cpa_wait0();          // K(kt) (and Q on first iter) resident
        __syncthreads();      // prior PV done -> V buffer free
        loadV(kt);            // V(kt) overlaps QK compute

        if (kt == 0) {
            // load the warp's Q fragments once (Q buffer is never overwritten)
#pragma unroll
            for (int kc = 0; kc < 12; kc++) {
                const int ra = w * 16 + (lane & 15);
                const int ca = kc * 2 + (lane >> 4);
                const uint32_t qa = sb + ra * ASTR_ + ((ca ^ (ra & 7)) * 16);
                ldmx4(qfh[kc], qa + OQH);
                ldmx4(qfl[kc], qa + OQL);
            }
        }

        const bool active = (k0 <= wkmax);
        float sacc[8][4];
        if (active) {
#pragma unroll
            for (int p = 0; p < 8; p++)
#pragma unroll
                for (int c = 0; c < 4; c++) sacc[p][c] = 0.f;

#pragma unroll
            for (int kc = 0; kc < 12; kc++) {
#pragma unroll
                for (int g16 = 0; g16 < 4; g16++) {
                    const int rb = g16 * 16 + (lane & 7) + ((lane >> 4) << 3);
                    const int cb = kc * 2 + ((lane >> 3) & 1);
                    const uint32_t ka = sb + rb * ASTR_ + ((cb ^ (rb & 7)) * 16);
                    uint32_t bKh[4], bKl[4];
                    ldmx4(bKh, ka + OKH);
                    ldmx4(bKl, ka + OKL);
#pragma unroll
                    for (int hh = 0; hh < 2; hh++) {
                        float* d = sacc[g16 * 2 + hh];
                        mma16816(d, qfh[kc], bKh + hh * 2);
                        mma16816(d, qfh[kc], bKl + hh * 2);
                        mma16816(d, qfl[kc], bKh + hh * 2);
                    }
                }
            }
        }

        cpa_wait0();          // V(kt) resident
        __syncthreads();      // all warps done with K(kt)
        if (kt + 1 < nkt) loadK(kt + 1);   // overlaps softmax + PV

        if (active) {
            if (k0 + 63 > q0 + w * 16) {
#pragma unroll
                for (int p = 0; p < 8; p++) {
                    const int colb = k0 + p * 8 + 2 * tq;
#pragma unroll
                    for (int c = 0; c < 4; c++) {
                        const int col = colb + (c & 1);
                        const int row = qr0 + ((c >> 1) << 3);
                        if (col > row) sacc[p][c] = -1e30f;
                    }
                }
            }

            float t0 = -1e30f, t1 = -1e30f;
#pragma unroll
            for (int p = 0; p < 8; p++) {
                t0 = fmaxf(t0, fmaxf(sacc[p][0], sacc[p][1]));
                t1 = fmaxf(t1, fmaxf(sacc[p][2], sacc[p][3]));
            }
            t0 = fmaxf(t0, __shfl_xor_sync(0xffffffffu, t0, 1));
            t0 = fmaxf(t0, __shfl_xor_sync(0xffffffffu, t0, 2));
            t1 = fmaxf(t1, __shfl_xor_sync(0xffffffffu, t1, 1));
            t1 = fmaxf(t1, __shfl_xor_sync(0xffffffffu, t1, 2));
            const float mn0 = fmaxf(m0, t0), mn1 = fmaxf(m1, t1);
            const float a0 = __expf(m0 - mn0), a1 = __expf(m1 - mn1);
            m0 = mn0; m1 = mn1;
            float s0 = 0.f, s1 = 0.f;
#pragma unroll
            for (int p = 0; p < 8; p++) {
                sacc[p][0] = __expf(sacc[p][0] - m0); s0 += sacc[p][0];
                sacc[p][1] = __expf(sacc[p][1] - m0); s0 += sacc[p][1];
                sacc[p][2] = __expf(sacc[p][2] - m1); s1 += sacc[p][2];
                sacc[p][3] = __expf(sacc[p][3] - m1); s1 += sacc[p][3];
            }
            s0 += __shfl_xor_sync(0xffffffffu, s0, 1);
            s0 += __shfl_xor_sync(0xffffffffu, s0, 2);
            s1 += __shfl_xor_sync(0xffffffffu, s1, 1);
            s1 += __shfl_xor_sync(0xffffffffu, s1, 2);
            l0 = l0 * a0 + s0;
            l1 = l1 * a1 + s1;

#pragma unroll
            for (int nt = 0; nt < 16; nt++) {
                oacc[nt][0] *= a0; oacc[nt][1] *= a0;
                oacc[nt][2] *= a1; oacc[nt][3] *= a1;
            }

#pragma unroll
            for (int kc2 = 0; kc2 < 4; kc2++) {
                uint32_t aPh[4], aPl[4];
#pragma unroll
                for (int u = 0; u < 4; u++) {
                    const float* pp = &sacc[kc2 * 2 + (u >> 1)][(u & 1) * 2];
                    const float p0 = pp[0], p1 = pp[1];
                    __nv_bfloat162 hv = __floats2bfloat162_rn(p0, p1);
                    aPh[u] = *(uint32_t*)&hv;
                    __nv_bfloat162 lv = __floats2bfloat162_rn(
                        p0 - __bfloat162float(hv.x), p1 - __bfloat162float(hv.y));
                    aPl[u] = *(uint32_t*)&lv;
                }
#pragma unroll
                for (int v16 = 0; v16 < 8; v16++) {
                    const int rv = kc2 * 16 + (lane & 7) + (((lane >> 3) & 1) << 3);
                    const int cv = v16 * 2 + (lane >> 4);
                    const uint32_t va = sb + rv * VSTR_ + ((cv ^ (rv & 7)) * 16);
                    uint32_t bVh[4], bVl[4];
                    ldmx4t(bVh, va + OVH);
                    ldmx4t(bVl, va + OVL);
#pragma unroll
                    for (int hh = 0; hh < 2; hh++) {
                        float* d = oacc[v16 * 2 + hh];
                        mma16816(d, aPh, bVh + hh * 2);
                        mma16816(d, aPh, bVl + hh * 2);
                        mma16816(d, aPl, bVh + hh * 2);
                    }
                }
            }
        }
    }

    // ---- epilogue ----
    const float i0 = 1.0f / l0, i1 = 1.0f / l1;
#pragma unroll
    for (int nt = 0; nt < 16; nt++) {
        const size_t base0 = (size_t)(rowg0 + w * 16 + g) * NO_ + h * 128 + nt * 8 + 2 * tq;
        const size_t base1 = base0 + (size_t)8 * NO_;
        float o0 = oacc[nt][0] * i0, o1 = oacc[nt][1] * i0;
        __nv_bfloat162 hv = __floats2bfloat162_rn(o0, o1);
        *(__nv_bfloat162*)(atth + base0) = hv;
        *(__nv_bfloat162*)(attl + base0) = __floats2bfloat162_rn(
            o0 - __bfloat162float(hv.x), o1 - __bfloat162float(hv.y));
        float o2 = oacc[nt][2] * i1, o3 = oacc[nt][3] * i1;
        __nv_bfloat162 hv2 = __floats2bfloat162_rn(o2, o3);
        *(__nv_bfloat162*)(atth + base1) = hv2;
        *(__nv_bfloat162*)(attl + base1) = __floats2bfloat162_rn(
            o2 - __bfloat162float(hv2.x), o3 - __bfloat162float(hv2.y));
    }
}

// ---------------- launch ----------------
extern "C" void kernel_launch(void* const* d_in, const int* in_sizes, int n_in,
                              void* d_out, int out_size)
{
    const float* x    = (const float*)d_in[0];
    const float* Wq   = (const float*)d_in[1];
    const float* Wdkv = (const float*)d_in[2];
    const float* Wkr  = (const float*)d_in[3];
    const float* Wukv = (const float*)d_in[4];
    const float* Wo   = (const float*)d_in[5];
    float* out = (float*)d_out;

    __nv_bfloat16 *xh, *xl, *ph, *pl, *kvh, *kvl, *atth, *attl;
    __nv_bfloat16 *wch, *wcl, *wuh, *wul, *woh, *wol;
    cudaGetSymbolAddress((void**)&xh,   g_xh);
    cudaGetSymbolAddress((void**)&xl,   g_xl);
    cudaGetSymbolAddress((void**)&ph,   g_ph);
    cudaGetSymbolAddress((void**)&pl,   g_pl);
    cudaGetSymbolAddress((void**)&kvh,  g_kvh);
    cudaGetSymbolAddress((void**)&kvl,  g_kvl);
    cudaGetSymbolAddress((void**)&atth, g_atth);
    cudaGetSymbolAddress((void**)&attl, g_attl);
    cudaGetSymbolAddress((void**)&wch,  g_wch);
    cudaGetSymbolAddress((void**)&wcl,  g_wcl);
    cudaGetSymbolAddress((void**)&wuh,  g_wuh);
    cudaGetSymbolAddress((void**)&wul,  g_wul);
    cudaGetSymbolAddress((void**)&woh,  g_woh);
    cudaGetSymbolAddress((void**)&wol,  g_wol);

    const float scale = 1.0f / sqrtf((float)(DH_ + DR_));
    dim3 blk(256);

    cudaFuncSetAttribute(gemm_mma, cudaFuncAttributeMaxDynamicSharedMemorySize, GEMM_SMEM);
    cudaFuncSetAttribute(attn_mma, cudaFuncAttributeMaxDynamicSharedMemorySize, ATT_SMEM);

    // 0: combined weight  [Wq*scale | Wkr | 0 | Wdkv]^T
    buildwc_k<<<dim3(CS_ / 32, DIM_ / 32), blk>>>(Wq, Wkr, Wdkv, wch, wcl, scale);
    // 1: x split
    split_k<<<ROWS * DIM_ / 4 / 256, blk>>>(x, xh, xl, ROWS * DIM_ / 4);
    // 2: Wukv transpose/split
    tsplitw_k<<<dim3(NKV_ / 32, LAT_ / 32), blk>>>(Wukv, wuh, wul, LAT_, NKV_, 1.0f);
    // 3 (ncu capture index): [q | kr | pad | ckv] = x @ Wc  -> hi/lo
    gemm_mma<<<dim3(CS_ / 128, ROWS / 128), blk, GEMM_SMEM>>>(
        xh, xl, wch, wcl, nullptr, ph, pl, ROWS, CS_, DIM_, DIM_, 1);
    // 4: Wo transpose/split
    tsplitw_k<<<dim3(DIM_ / 32, NO_ / 32), blk>>>(Wo, woh, wol, NO_, DIM_, 1.0f);
    // 5: kv = ckv @ Wukv  (ckv in place from combined buffer, lda=CS_)
    gemm_mma<<<dim3(NKV_ / 128, ROWS / 128), blk, GEMM_SMEM>>>(
        ph + 3200, pl + 3200, wuh, wul, nullptr, kvh, kvl, ROWS, NKV_, LAT_, CS_, 1);
    // 6: RoPE in hi/lo domain
    rope_hl<<<(ROWS * 17 * 32 + 255) / 256, blk>>>(ph, pl);
    // 7: attention
    attn_mma<<<dim3(SS / 128, HH, BB), blk, ATT_SMEM>>>(ph, pl, kvh, kvl, atth, attl);
    // 8: out = att @ Wo  -> fp32
    gemm_mma<<<dim3(DIM_ / 128, ROWS / 128), blk, GEMM_SMEM>>>(
        atth, attl, woh, wol, out, nullptr, nullptr, ROWS, DIM_, NO_, NO_, 0);
}

// round 14
// speedup vs baseline: 1.0575x; 1.0575x over previous
#include <cuda_runtime.h>
#include <cuda_bf16.h>
#include <math.h>
#include <stdint.h>

// ---------------- problem constants ----------------
#define BB   2
#define SS   2048
#define DIM_ 2048
#define HH   16
#define DH_  128
#define LAT_ 512
#define DR_  64
#define NQ_  (HH * (DH_ + DR_))   // 3072
#define CS_  3712                 // combined q||kr||pad||ckv stride (29 tiles)
#define NKV_ (HH * 2 * DH_)       // 4096
#define NO_  (HH * DH_)           // 2048
#define ROWS (BB * SS)            // 4096

// ---------------- scratch (device globals; no allocation allowed) ----------
__device__ __align__(16) __nv_bfloat16 g_xh   [ROWS * (size_t)DIM_];
__device__ __align__(16) __nv_bfloat16 g_xl   [ROWS * (size_t)DIM_];
__device__ __align__(16) __nv_bfloat16 g_ph   [ROWS * (size_t)CS_];   // q|kr|pad|ckv hi
__device__ __align__(16) __nv_bfloat16 g_pl   [ROWS * (size_t)CS_];   // lo
__device__ __align__(16) __nv_bfloat16 g_kvh  [ROWS * (size_t)NKV_];
__device__ __align__(16) __nv_bfloat16 g_kvl  [ROWS * (size_t)NKV_];
__device__ __align__(16) __nv_bfloat16 g_atth [ROWS * (size_t)NO_];
__device__ __align__(16) __nv_bfloat16 g_attl [ROWS * (size_t)NO_];
// combined weight [Wq*scale | Wkr | 0 | Wdkv] transposed: CS_ x DIM_
__device__ __align__(16) __nv_bfloat16 g_wch  [CS_  * (size_t)DIM_];
__device__ __align__(16) __nv_bfloat16 g_wcl  [CS_  * (size_t)DIM_];
__device__ __align__(16) __nv_bfloat16 g_wuh  [NKV_ * (size_t)LAT_];
__device__ __align__(16) __nv_bfloat16 g_wul  [NKV_ * (size_t)LAT_];
__device__ __align__(16) __nv_bfloat16 g_woh  [DIM_ * (size_t)NO_];
__device__ __align__(16) __nv_bfloat16 g_wol  [DIM_ * (size_t)NO_];

// ---------------- PTX helpers (arch-portable) ----------
__device__ __forceinline__ uint32_t smem_u32(const void* p) {
    uint32_t a;
    asm("{ .reg .u64 t; cvta.to.shared.u64 t, %1; cvt.u32.u64 %0, t; }"
        : "=r"(a) : "l"(p));
    return a;
}
__device__ __forceinline__ void cpa16(uint32_t dst, const void* src) {
    asm volatile("cp.async.cg.shared.global [%0], [%1], 16;"
                 :: "r"(dst), "l"(src) : "memory");
}
__device__ __forceinline__ void cpa_commit() {
    asm volatile("cp.async.commit_group;" ::: "memory");
}
__device__ __forceinline__ void cpa_wait0() {
    asm volatile("cp.async.wait_group 0;" ::: "memory");
}
__device__ __forceinline__ void cpa_wait1() {
    asm volatile("cp.async.wait_group 1;" ::: "memory");
}
__device__ __forceinline__ void ldmx4(uint32_t* r, uint32_t addr) {
    asm volatile("ldmatrix.sync.aligned.m8n8.x4.shared.b16 {%0,%1,%2,%3}, [%4];"
        : "=r"(r[0]), "=r"(r[1]), "=r"(r[2]), "=r"(r[3]) : "r"(addr));
}
__device__ __forceinline__ void ldmx4t(uint32_t* r, uint32_t addr) {
    asm volatile("ldmatrix.sync.aligned.m8n8.x4.trans.shared.b16 {%0,%1,%2,%3}, [%4];"
        : "=r"(r[0]), "=r"(r[1]), "=r"(r[2]), "=r"(r[3]) : "r"(addr));
}
__device__ __forceinline__ void mma16816(float* d, const uint32_t* a, const uint32_t* b) {
    asm volatile(
        "mma.sync.aligned.m16n8k16.row.col.f32.bf16.bf16.f32 "
        "{%0,%1,%2,%3}, {%4,%5,%6,%7}, {%8,%9}, {%0,%1,%2,%3};"
        : "+f"(d[0]), "+f"(d[1]), "+f"(d[2]), "+f"(d[3])
        : "r"(a[0]), "r"(a[1]), "r"(a[2]), "r"(a[3]), "r"(b[0]), "r"(b[1]));
}

// ---------------- elementwise split (x only) ----------------
__global__ __launch_bounds__(256) void split_k(
    const float* __restrict__ A, __nv_bfloat16* __restrict__ h,
    __nv_bfloat16* __restrict__ l, int n4)
{
    int i = blockIdx.x * 256 + threadIdx.x;
    if (i >= n4) return;
    float4 v = *(const float4*)(A + (size_t)i * 4);
    __nv_bfloat16 hx = __float2bfloat16(v.x), hy = __float2bfloat16(v.y);
    __nv_bfloat16 hz = __float2bfloat16(v.z), hw = __float2bfloat16(v.w);
    __nv_bfloat162* hp = (__nv_bfloat162*)(h + (size_t)i * 4);
    hp[0] = __nv_bfloat162(hx, hy);
    hp[1] = __nv_bfloat162(hz, hw);
    __nv_bfloat162* lp = (__nv_bfloat162*)(l + (size_t)i * 4);
    lp[0] = __nv_bfloat162(__float2bfloat16(v.x - __bfloat162float(hx)),
                           __float2bfloat16(v.y - __bfloat162float(hy)));
    lp[1] = __nv_bfloat162(__float2bfloat16(v.z - __bfloat162float(hz)),
                           __float2bfloat16(v.w - __bfloat162float(hw)));
}

// ---------------- transpose + split weights: T[n][k] = alpha*B[k][n] -------
__global__ __launch_bounds__(256) void tsplitw_k(
    const float* __restrict__ B, __nv_bfloat16* __restrict__ Th,
    __nv_bfloat16* __restrict__ Tl, int K, int N, float alpha)
{
    __shared__ float tile[32][33];
    const int tx = threadIdx.x & 31, ty = threadIdx.x >> 5;
    const int n0 = blockIdx.x * 32, k0 = blockIdx.y * 32;
#pragma unroll
    for (int i = 0; i < 32; i += 8)
        tile[ty + i][tx] = B[(size_t)(k0 + ty + i) * N + n0 + tx];
    __syncthreads();
#pragma unroll
    for (int i = 0; i < 32; i += 8) {
        float v = alpha * tile[tx][ty + i];
        __nv_bfloat16 h = __float2bfloat16(v);
        size_t o = (size_t)(n0 + ty + i) * K + k0 + tx;
        Th[o] = h;
        Tl[o] = __float2bfloat16(v - __bfloat162float(h));
    }
}

// ---------------- build combined weight [Wq*scale | Wkr | 0 | Wdkv]^T -----
__global__ __launch_bounds__(256) void buildwc_k(
    const float* __restrict__ Wq, const float* __restrict__ Wkr,
    const float* __restrict__ Wdkv, __nv_bfloat16* __restrict__ Th,
    __nv_bfloat16* __restrict__ Tl, float scale)
{
    __shared__ float tile[32][33];
    const int tx = threadIdx.x & 31, ty = threadIdx.x >> 5;
    const int n0 = blockIdx.x * 32, k0 = blockIdx.y * 32;

    const float* src; int Nsrc, nc; float alpha;
    if (n0 < 3072)      { src = Wq;   Nsrc = NQ_;  nc = n0;        alpha = scale; }
    else if (n0 < 3136) { src = Wkr;  Nsrc = DR_;  nc = n0 - 3072; alpha = 1.0f; }
    else if (n0 < 3200) { src = 0;    Nsrc = 0;    nc = 0;         alpha = 0.0f; }
    else                { src = Wdkv; Nsrc = LAT_; nc = n0 - 3200; alpha = 1.0f; }

    if (src) {
#pragma unroll
        for (int i = 0; i < 32; i += 8)
            tile[ty + i][tx] = src[(size_t)(k0 + ty + i) * Nsrc + nc + tx];
    } else {
#pragma unroll
        for (int i = 0; i < 32; i += 8)
            tile[ty + i][tx] = 0.f;
    }
    __syncthreads();
#pragma unroll
    for (int i = 0; i < 32; i += 8) {
        float v = alpha * tile[tx][ty + i];
        __nv_bfloat16 h = __float2bfloat16(v);
        size_t o = (size_t)(n0 + ty + i) * DIM_ + k0 + tx;
        Th[o] = h;
        Tl[o] = __float2bfloat16(v - __bfloat162float(h));
    }
}

// ---------------- bf16 split-2 HMMA GEMM, 3-stage, 2 CTAs/SM ---------------
// Pass-major MMA ordering: consecutive MMAs hit distinct accumulators.
#define STG_A 8192
#define STG   32768
#define GEMM_SMEM (3 * STG)

__global__ __launch_bounds__(256, 2) void gemm_mma(
    const __nv_bfloat16* __restrict__ Ah, const __nv_bfloat16* __restrict__ Al,
    const __nv_bfloat16* __restrict__ Bh, const __nv_bfloat16* __restrict__ Bl,
    float* __restrict__ C, __nv_bfloat16* __restrict__ Ch,
    __nv_bfloat16* __restrict__ Cl, int M, int N, int K, int lda, int out_hl)
{
    extern __shared__ char smc[];
    const uint32_t sb = smem_u32(smc);
    const int t = threadIdx.x, wid = t >> 5, lane = t & 31;
    const int m0 = blockIdx.y * 128, n0 = blockIdx.x * 128;
    const int wr = (wid & 3) * 32, wc = (wid >> 2) * 64;

    float acc[2][8][4];
#pragma unroll
    for (int a = 0; a < 2; a++)
#pragma unroll
        for (int b = 0; b < 8; b++)
#pragma unroll
            for (int c = 0; c < 4; c++) acc[a][b][c] = 0.f;

    const int nk = K >> 5;

    auto load_stage = [&](int kc, int s) {
        const uint32_t base = sb + s * STG;
#pragma unroll
        for (int i = 0; i < 2; i++) {
            const int idx = t + i * 256;
            const int r = idx >> 2, c = idx & 3;
            const uint32_t sw = (uint32_t)(r * 64 + ((c ^ ((r >> 1) & 3)) * 16));
            const size_t ga = (size_t)(m0 + r) * lda + kc * 32 + c * 8;
            const size_t gb = (size_t)(n0 + r) * K + kc * 32 + c * 8;
            cpa16(base + sw,             Ah + ga);
            cpa16(base + STG_A + sw,     Al + ga);
            cpa16(base + 2 * STG_A + sw, Bh + gb);
            cpa16(base + 3 * STG_A + sw, Bl + gb);
        }
        cpa_commit();
    };

    // 3 stages, prefetch distance 2, one barrier per iteration.
    load_stage(0, 0);
    load_stage(1, 1);

    for (int kc = 0; kc < nk; kc++) {
        const int s = kc % 3;
        cpa_wait1();          // load(kc) resident (<=1 group pending)
        __syncthreads();      // all warps done with the stage being refilled
        if (kc + 2 < nk) load_stage(kc + 2, (kc + 2) % 3);
        else cpa_commit();    // keep group accounting aligned
        const uint32_t base = sb + s * STG;

#pragma unroll
        for (int ks = 0; ks < 2; ks++) {
            uint32_t ah[2][4], al[2][4];
#pragma unroll
            for (int mi = 0; mi < 2; mi++) {
                const int r = wr + mi * 16 + (lane & 15);
                const int ch = ks * 2 + (lane >> 4);
                const uint32_t ad = base + r * 64 + ((ch ^ ((r >> 1) & 3)) * 16);
                ldmx4(ah[mi], ad);
                ldmx4(al[mi], ad + STG_A);
            }
#pragma unroll
            for (int p = 0; p < 4; p++) {
                const int r = wc + p * 16 + (lane & 7) + ((lane >> 4) << 3);
                const int ch = ks * 2 + ((lane >> 3) & 1);
                const uint32_t bd = base + 2 * STG_A + r * 64 + ((ch ^ ((r >> 1) & 3)) * 16);
                uint32_t bh[4], bl[4];
                ldmx4(bh, bd);
                ldmx4(bl, bd + STG_A);
                // pass-major: 4 distinct accumulators between dependent MMAs
#pragma unroll
                for (int hh = 0; hh < 2; hh++)
#pragma unroll
                    for (int mi = 0; mi < 2; mi++)
                        mma16816(acc[mi][p * 2 + hh], ah[mi], bh + hh * 2);
#pragma unroll
                for (int hh = 0; hh < 2; hh++)
#pragma unroll
                    for (int mi = 0; mi < 2; mi++)
                        mma16816(acc[mi][p * 2 + hh], ah[mi], bl + hh * 2);
#pragma unroll
                for (int hh = 0; hh < 2; hh++)
#pragma unroll
                    for (int mi = 0; mi < 2; mi++)
                        mma16816(acc[mi][p * 2 + hh], al[mi], bh + hh * 2);
            }
        }
    }

    // epilogue (C row stride == N)
#pragma unroll
    for (int mi = 0; mi < 2; mi++) {
#pragma unroll
        for (int ni = 0; ni < 8; ni++) {
            const int r0 = m0 + wr + mi * 16 + (lane >> 2);
            const int c0 = n0 + wc + ni * 8 + (lane & 3) * 2;
            if (out_hl) {
#pragma unroll
                for (int half = 0; half < 2; half++) {
                    const size_t o = (size_t)(r0 + half * 8) * N + c0;
                    const float v0 = acc[mi][ni][half * 2 + 0];
                    const float v1 = acc[mi][ni][half * 2 + 1];
                    __nv_bfloat162 hv = __floats2bfloat162_rn(v0, v1);
                    *(__nv_bfloat162*)(Ch + o) = hv;
                    *(__nv_bfloat162*)(Cl + o) = __floats2bfloat162_rn(
                        v0 - __bfloat162float(hv.x), v1 - __bfloat162float(hv.y));
                }
            } else {
                float2 v0, v1;
                v0.x = acc[mi][ni][0]; v0.y = acc[mi][ni][1];
                v1.x = acc[mi][ni][2]; v1.y = acc[mi][ni][3];
                *(float2*)&C[(size_t)r0 * N + c0]       = v0;
                *(float2*)&C[(size_t)(r0 + 8) * N + c0] = v1;
            }
        }
    }
}

// ---------------- RoPE in hi/lo domain (q rope blocks + kr block) ---------
__global__ void rope_hl(__nv_bfloat16* __restrict__ h, __nv_bfloat16* __restrict__ l)
{
    int idx = blockIdx.x * blockDim.x + threadIdx.x;   // ROWS*17*32
    if (idx >= ROWS * 17 * 32) return;
    int i   = idx & 31;
    int u   = (idx >> 5) % 17;
    int row = (idx >> 5) / 17;
    int pos = row & (SS - 1);
    float inv = powf(10000.0f, -(float)i / 32.0f);
    float ang = (float)pos * inv;
    float s, c; sincosf(ang, &s, &c);
    size_t base = (size_t)row * CS_ + (u < 16 ? u * 192 + 128 : 3072);
    float x1 = __bfloat162float(h[base + i])      + __bfloat162float(l[base + i]);
    float x2 = __bfloat162float(h[base + i + 32]) + __bfloat162float(l[base + i + 32]);
    float r1 = x1 * c - x2 * s;
    float r2 = x2 * c + x1 * s;
    __nv_bfloat16 h1 = __float2bfloat16(r1), h2 = __float2bfloat16(r2);
    h[base + i]      = h1;
    l[base + i]      = __float2bfloat16(r1 - __bfloat162float(h1));
    h[base + i + 32] = h2;
    l[base + i + 32] = __float2bfloat16(r2 - __bfloat162float(h2));
}

// ---------------- flash attention, split-2 bf16 HMMA, overlapped loads ----
#define ASTR_ 384
#define VSTR_ 256
#define OQH 0
#define OQL 49152
#define OKH 98304
#define OKL 122880
#define OVH 147456
#define OVL 163840
#define ATT_SMEM 180224

__global__ __launch_bounds__(256, 1) void attn_mma(
    const __nv_bfloat16* __restrict__ qh,  const __nv_bfloat16* __restrict__ ql,
    const __nv_bfloat16* __restrict__ kvh, const __nv_bfloat16* __restrict__ kvl,
    __nv_bfloat16* __restrict__ atth, __nv_bfloat16* __restrict__ attl)
{
    extern __shared__ char smc[];
    const uint32_t sb = smem_u32(smc);
    const int t = threadIdx.x, w = t >> 5, lane = t & 31;
    const int qt = gridDim.x - 1 - blockIdx.x;   // heavy tiles first
    const int h = blockIdx.y, b = blockIdx.z;
    const int q0 = qt * 128;
    const int rowg0 = b * SS + q0;
    const int g = lane >> 2, tq = lane & 3;
    const int qr0 = q0 + w * 16 + g;

    auto loadK = [&](int kt) {
        const int k0 = kt * 64;
#pragma unroll
        for (int it = 0; it < 6; it++) {
            const int idx = t + it * 256;        // 64*24
            const int r = idx / 24, c = idx % 24;
            const uint32_t dst = sb + r * ASTR_ + ((c ^ (r & 7)) * 16);
            const size_t rg = (size_t)(b * SS + k0 + r);
            if (c < 16) {
                const size_t go = rg * NKV_ + h * 256 + c * 8;
                cpa16(dst + OKH, kvh + go);
                cpa16(dst + OKL, kvl + go);
            } else {
                const size_t go = rg * CS_ + 3072 + (c - 16) * 8;
                cpa16(dst + OKH, qh + go);
                cpa16(dst + OKL, ql + go);
            }
        }
        cpa_commit();
    };
    auto loadV = [&](int kt) {
        const int k0 = kt * 64;
#pragma unroll
        for (int it = 0; it < 4; it++) {
            const int idx = t + it * 256;        // 64*16
            const int r = idx >> 4, c = idx & 15;
            const uint32_t dst = sb + r * VSTR_ + ((c ^ (r & 7)) * 16);
            const size_t go = (size_t)(b * SS + k0 + r) * NKV_ + h * 256 + 128 + c * 8;
            cpa16(dst + OVH, kvh + go);
            cpa16(dst + OVL, kvl + go);
        }
        cpa_commit();
    };

    // ---- prologue: Q tile + K(0) ----
#pragma unroll
    for (int it = 0; it < 12; it++) {
        const int idx = t + it * 256;            // 128*24
        const int r = idx / 24, c = idx % 24;
        const uint32_t dst = sb + r * ASTR_ + ((c ^ (r & 7)) * 16);
        const size_t go = (size_t)(rowg0 + r) * CS_ + h * 192 + c * 8;
        cpa16(dst + OQH, qh + go);
        cpa16(dst + OQL, ql + go);
    }
    cpa_commit();
    loadK(0);

    float m0 = -1e30f, m1 = -1e30f, l0 = 0.f, l1 = 0.f;
    float oacc[16][4];
#pragma unroll
    for (int i = 0; i < 16; i++)
#pragma unroll
        for (int j = 0; j < 4; j++) oacc[i][j] = 0.f;

    const int nkt = 2 * qt + 2;
    const int wkmax = q0 + w * 16 + 15;

    for (int kt = 0; kt < nkt; kt++) {
        const int k0 = kt * 64;
        cpa_wait0();          // K(kt) (and Q on first iter) resident
        __syncthreads();      // prior PV done -> V buffer free
        loadV(kt);            // V(kt) overlaps QK compute

        const bool active = (k0 <= wkmax);
        float sacc[8][4];
        if (active) {
#pragma unroll
            for (int p = 0; p < 8; p++)
#pragma unroll
                for (int c = 0; c < 4; c++) sacc[p][c] = 0.f;

            for (int kc = 0; kc < 12; kc++) {
                const int ra = w * 16 + (lane & 15);
                const int ca = kc * 2 + (lane >> 4);
                const uint32_t qa = sb + ra * ASTR_ + ((ca ^ (ra & 7)) * 16);
                uint32_t aQh[4], aQl[4];
                ldmx4(aQh, qa + OQH);
                ldmx4(aQl, qa + OQL);
#pragma unroll
                for (int g16 = 0; g16 < 4; g16++) {
                    const int rb = g16 * 16 + (lane & 7) + ((lane >> 4) << 3);
                    const int cb = kc * 2 + ((lane >> 3) & 1);
                    const uint32_t ka = sb + rb * ASTR_ + ((cb ^ (rb & 7)) * 16);
                    uint32_t bKh[4], bKl[4];
                    ldmx4(bKh, ka + OKH);
                    ldmx4(bKl, ka + OKL);
                    // pass-major ordering (2 distinct accumulators per pass)
#pragma unroll
                    for (int hh = 0; hh < 2; hh++)
                        mma16816(sacc[g16 * 2 + hh], aQh, bKh + hh * 2);
#pragma unroll
                    for (int hh = 0; hh < 2; hh++)
                        mma16816(sacc[g16 * 2 + hh], aQh, bKl + hh * 2);
#pragma unroll
                    for (int hh = 0; hh < 2; hh++)
                        mma16816(sacc[g16 * 2 + hh], aQl, bKh + hh * 2);
                }
            }
        }

        cpa_wait0();          // V(kt) resident
        __syncthreads();      // all warps done with K(kt)
        if (kt + 1 < nkt) loadK(kt + 1);   // overlaps softmax + PV

        if (active) {
            if (k0 + 63 > q0 + w * 16) {
#pragma unroll
                for (int p = 0; p < 8; p++) {
                    const int colb = k0 + p * 8 + 2 * tq;
#pragma unroll
                    for (int c = 0; c < 4; c++) {
                        const int col = colb + (c & 1);
                        const int row = qr0 + ((c >> 1) << 3);
                        if (col > row) sacc[p][c] = -1e30f;
                    }
                }
            }

            float t0 = -1e30f, t1 = -1e30f;
#pragma unroll
            for (int p = 0; p < 8; p++) {
                t0 = fmaxf(t0, fmaxf(sacc[p][0], sacc[p][1]));
                t1 = fmaxf(t1, fmaxf(sacc[p][2], sacc[p][3]));
            }
            t0 = fmaxf(t0, __shfl_xor_sync(0xffffffffu, t0, 1));
            t0 = fmaxf(t0, __shfl_xor_sync(0xffffffffu, t0, 2));
            t1 = fmaxf(t1, __shfl_xor_sync(0xffffffffu, t1, 1));
            t1 = fmaxf(t1, __shfl_xor_sync(0xffffffffu, t1, 2));
            const float mn0 = fmaxf(m0, t0), mn1 = fmaxf(m1, t1);
            const float a0 = __expf(m0 - mn0), a1 = __expf(m1 - mn1);
            m0 = mn0; m1 = mn1;
            float s0 = 0.f, s1 = 0.f;
#pragma unroll
            for (int p = 0; p < 8; p++) {
                sacc[p][0] = __expf(sacc[p][0] - m0); s0 += sacc[p][0];
                sacc[p][1] = __expf(sacc[p][1] - m0); s0 += sacc[p][1];
                sacc[p][2] = __expf(sacc[p][2] - m1); s1 += sacc[p][2];
                sacc[p][3] = __expf(sacc[p][3] - m1); s1 += sacc[p][3];
            }
            s0 += __shfl_xor_sync(0xffffffffu, s0, 1);
            s0 += __shfl_xor_sync(0xffffffffu, s0, 2);
            s1 += __shfl_xor_sync(0xffffffffu, s1, 1);
            s1 += __shfl_xor_sync(0xffffffffu, s1, 2);
            l0 = l0 * a0 + s0;
            l1 = l1 * a1 + s1;

#pragma unroll
            for (int nt = 0; nt < 16; nt++) {
                oacc[nt][0] *= a0; oacc[nt][1] *= a0;
                oacc[nt][2] *= a1; oacc[nt][3] *= a1;
            }

#pragma unroll
            for (int kc2 = 0; kc2 < 4; kc2++) {
                uint32_t aPh[4], aPl[4];
#pragma unroll
                for (int u = 0; u < 4; u++) {
                    const float* pp = &sacc[kc2 * 2 + (u >> 1)][(u & 1) * 2];
                    const float p0 = pp[0], p1 = pp[1];
                    __nv_bfloat162 hv = __floats2bfloat162_rn(p0, p1);
                    aPh[u] = *(uint32_t*)&hv;
                    __nv_bfloat162 lv = __floats2bfloat162_rn(
                        p0 - __bfloat162float(hv.x), p1 - __bfloat162float(hv.y));
                    aPl[u] = *(uint32_t*)&lv;
                }
#pragma unroll
                for (int v16 = 0; v16 < 8; v16++) {
                    const int rv = kc2 * 16 + (lane & 7) + (((lane >> 3) & 1) << 3);
                    const int cv = v16 * 2 + (lane >> 4);
                    const uint32_t va = sb + rv * VSTR_ + ((cv ^ (rv & 7)) * 16);
                    uint32_t bVh[4], bVl[4];
                    ldmx4t(bVh, va + OVH);
                    ldmx4t(bVl, va + OVL);
                    // pass-major ordering
#pragma unroll
                    for (int hh = 0; hh < 2; hh++)
                        mma16816(oacc[v16 * 2 + hh], aPh, bVh + hh * 2);
#pragma unroll
                    for (int hh = 0; hh < 2; hh++)
                        mma16816(oacc[v16 * 2 + hh], aPh, bVl + hh * 2);
#pragma unroll
                    for (int hh = 0; hh < 2; hh++)
                        mma16816(oacc[v16 * 2 + hh], aPl, bVh + hh * 2);
                }
            }
        }
    }

    // ---- epilogue ----
    const float i0 = 1.0f / l0, i1 = 1.0f / l1;
#pragma unroll
    for (int nt = 0; nt < 16; nt++) {
        const size_t base0 = (size_t)(rowg0 + w * 16 + g) * NO_ + h * 128 + nt * 8 + 2 * tq;
        const size_t base1 = base0 + (size_t)8 * NO_;
        float o0 = oacc[nt][0] * i0, o1 = oacc[nt][1] * i0;
        __nv_bfloat162 hv = __floats2bfloat162_rn(o0, o1);
        *(__nv_bfloat162*)(atth + base0) = hv;
        *(__nv_bfloat162*)(attl + base0) = __floats2bfloat162_rn(
            o0 - __bfloat162float(hv.x), o1 - __bfloat162float(hv.y));
        float o2 = oacc[nt][2] * i1, o3 = oacc[nt][3] * i1;
        __nv_bfloat162 hv2 = __floats2bfloat162_rn(o2, o3);
        *(__nv_bfloat162*)(atth + base1) = hv2;
        *(__nv_bfloat162*)(attl + base1) = __floats2bfloat162_rn(
            o2 - __bfloat162float(hv2.x), o3 - __bfloat162float(hv2.y));
    }
}

// ---------------- launch ----------------
extern "C" void kernel_launch(void* const* d_in, const int* in_sizes, int n_in,
                              void* d_out, int out_size)
{
    const float* x    = (const float*)d_in[0];
    const float* Wq   = (const float*)d_in[1];
    const float* Wdkv = (const float*)d_in[2];
    const float* Wkr  = (const float*)d_in[3];
    const float* Wukv = (const float*)d_in[4];
    const float* Wo   = (const float*)d_in[5];
    float* out = (float*)d_out;

    __nv_bfloat16 *xh, *xl, *ph, *pl, *kvh, *kvl, *atth, *attl;
    __nv_bfloat16 *wch, *wcl, *wuh, *wul, *woh, *wol;
    cudaGetSymbolAddress((void**)&xh,   g_xh);
    cudaGetSymbolAddress((void**)&xl,   g_xl);
    cudaGetSymbolAddress((void**)&ph,   g_ph);
    cudaGetSymbolAddress((void**)&pl,   g_pl);
    cudaGetSymbolAddress((void**)&kvh,  g_kvh);
    cudaGetSymbolAddress((void**)&kvl,  g_kvl);
    cudaGetSymbolAddress((void**)&atth, g_atth);
    cudaGetSymbolAddress((void**)&attl, g_attl);
    cudaGetSymbolAddress((void**)&wch,  g_wch);
    cudaGetSymbolAddress((void**)&wcl,  g_wcl);
    cudaGetSymbolAddress((void**)&wuh,  g_wuh);
    cudaGetSymbolAddress((void**)&wul,  g_wul);
    cudaGetSymbolAddress((void**)&woh,  g_woh);
    cudaGetSymbolAddress((void**)&wol,  g_wol);

    const float scale = 1.0f / sqrtf((float)(DH_ + DR_));
    dim3 blk(256);

    cudaFuncSetAttribute(gemm_mma, cudaFuncAttributeMaxDynamicSharedMemorySize, GEMM_SMEM);
    cudaFuncSetAttribute(attn_mma, cudaFuncAttributeMaxDynamicSharedMemorySize, ATT_SMEM);

    // 0: combined weight  [Wq*scale | Wkr | 0 | Wdkv]^T
    buildwc_k<<<dim3(CS_ / 32, DIM_ / 32), blk>>>(Wq, Wkr, Wdkv, wch, wcl, scale);
    // 1: x split
    split_k<<<ROWS * DIM_ / 4 / 256, blk>>>(x, xh, xl, ROWS * DIM_ / 4);
    // 2: Wukv transpose/split
    tsplitw_k<<<dim3(NKV_ / 32, LAT_ / 32), blk>>>(Wukv, wuh, wul, LAT_, NKV_, 1.0f);
    // 3 (ncu capture index): [q | kr | pad | ckv] = x @ Wc  -> hi/lo
    gemm_mma<<<dim3(CS_ / 128, ROWS / 128), blk, GEMM_SMEM>>>(
        xh, xl, wch, wcl, nullptr, ph, pl, ROWS, CS_, DIM_, DIM_, 1);
    // 4: Wo transpose/split
    tsplitw_k<<<dim3(DIM_ / 32, NO_ / 32), blk>>>(Wo, woh, wol, NO_, DIM_, 1.0f);
    // 5: kv = ckv @ Wukv  (ckv in place from combined buffer, lda=CS_)
    gemm_mma<<<dim3(NKV_ / 128, ROWS / 128), blk, GEMM_SMEM>>>(
        ph + 3200, pl + 3200, wuh, wul, nullptr, kvh, kvl, ROWS, NKV_, LAT_, CS_, 1);
    // 6: RoPE in hi/lo domain
    rope_hl<<<(ROWS * 17 * 32 + 255) / 256, blk>>>(ph, pl);
    // 7: attention
    attn_mma<<<dim3(SS / 128, HH, BB), blk, ATT_SMEM>>>(ph, pl, kvh, kvl, atth, attl);
    // 8: out = att @ Wo  -> fp32
    gemm_mma<<<dim3(DIM_ / 128, ROWS / 128), blk, GEMM_SMEM>>>(
        atth, attl, woh, wol, out, nullptr, nullptr, ROWS, DIM_, NO_, NO_, 0);
}

// round 15
// speedup vs baseline: 1.1066x; 1.0464x over previous
#include <cuda_runtime.h>
#include <cuda_bf16.h>
#include <math.h>
#include <stdint.h>

// ---------------- problem constants ----------------
#define BB   2
#define SS   2048
#define DIM_ 2048
#define HH   16
#define DH_  128
#define LAT_ 512
#define DR_  64
#define NQ_  (HH * (DH_ + DR_))   // 3072
#define CS_  3712                 // combined q||kr||pad||ckv stride (29 tiles)
#define NKV_ (HH * 2 * DH_)       // 4096
#define NO_  (HH * DH_)           // 2048
#define ROWS (BB * SS)            // 4096

// ---------------- scratch (device globals; no allocation allowed) ----------
__device__ __align__(16) __nv_bfloat16 g_xh   [ROWS * (size_t)DIM_];
__device__ __align__(16) __nv_bfloat16 g_xl   [ROWS * (size_t)DIM_];
__device__ __align__(16) __nv_bfloat16 g_ph   [ROWS * (size_t)CS_];   // q|kr|pad|ckv hi
__device__ __align__(16) __nv_bfloat16 g_pl   [ROWS * (size_t)CS_];   // lo
__device__ __align__(16) __nv_bfloat16 g_kvh  [ROWS * (size_t)NKV_];
__device__ __align__(16) __nv_bfloat16 g_kvl  [ROWS * (size_t)NKV_];
__device__ __align__(16) __nv_bfloat16 g_atth [ROWS * (size_t)NO_];
__device__ __align__(16) __nv_bfloat16 g_attl [ROWS * (size_t)NO_];
// combined weight [Wq*scale | Wkr | 0 | Wdkv] transposed: CS_ x DIM_
__device__ __align__(16) __nv_bfloat16 g_wch  [CS_  * (size_t)DIM_];
__device__ __align__(16) __nv_bfloat16 g_wcl  [CS_  * (size_t)DIM_];
__device__ __align__(16) __nv_bfloat16 g_wuh  [NKV_ * (size_t)LAT_];
__device__ __align__(16) __nv_bfloat16 g_wul  [NKV_ * (size_t)LAT_];
__device__ __align__(16) __nv_bfloat16 g_woh  [DIM_ * (size_t)NO_];
__device__ __align__(16) __nv_bfloat16 g_wol  [DIM_ * (size_t)NO_];

// ---------------- PTX helpers (arch-portable) ----------
__device__ __forceinline__ uint32_t smem_u32(const void* p) {
    uint32_t a;
    asm("{ .reg .u64 t; cvta.to.shared.u64 t, %1; cvt.u32.u64 %0, t; }"
        : "=r"(a) : "l"(p));
    return a;
}
__device__ __forceinline__ void cpa16(uint32_t dst, const void* src) {
    asm volatile("cp.async.cg.shared.global [%0], [%1], 16;"
                 :: "r"(dst), "l"(src) : "memory");
}
__device__ __forceinline__ void cpa_commit() {
    asm volatile("cp.async.commit_group;" ::: "memory");
}
__device__ __forceinline__ void cpa_wait0() {
    asm volatile("cp.async.wait_group 0;" ::: "memory");
}
__device__ __forceinline__ void cpa_wait1() {
    asm volatile("cp.async.wait_group 1;" ::: "memory");
}
__device__ __forceinline__ void ldmx4(uint32_t* r, uint32_t addr) {
    asm volatile("ldmatrix.sync.aligned.m8n8.x4.shared.b16 {%0,%1,%2,%3}, [%4];"
        : "=r"(r[0]), "=r"(r[1]), "=r"(r[2]), "=r"(r[3]) : "r"(addr));
}
__device__ __forceinline__ void ldmx4t(uint32_t* r, uint32_t addr) {
    asm volatile("ldmatrix.sync.aligned.m8n8.x4.trans.shared.b16 {%0,%1,%2,%3}, [%4];"
        : "=r"(r[0]), "=r"(r[1]), "=r"(r[2]), "=r"(r[3]) : "r"(addr));
}
__device__ __forceinline__ void mma16816(float* d, const uint32_t* a, const uint32_t* b) {
    asm volatile(
        "mma.sync.aligned.m16n8k16.row.col.f32.bf16.bf16.f32 "
        "{%0,%1,%2,%3}, {%4,%5,%6,%7}, {%8,%9}, {%0,%1,%2,%3};"
        : "+f"(d[0]), "+f"(d[1]), "+f"(d[2]), "+f"(d[3])
        : "r"(a[0]), "r"(a[1]), "r"(a[2]), "r"(a[3]), "r"(b[0]), "r"(b[1]));
}

// ---------------- elementwise split (x only) ----------------
__global__ __launch_bounds__(256) void split_k(
    const float* __restrict__ A, __nv_bfloat16* __restrict__ h,
    __nv_bfloat16* __restrict__ l, int n4)
{
    int i = blockIdx.x * 256 + threadIdx.x;
    if (i >= n4) return;
    float4 v = *(const float4*)(A + (size_t)i * 4);
    __nv_bfloat16 hx = __float2bfloat16(v.x), hy = __float2bfloat16(v.y);
    __nv_bfloat16 hz = __float2bfloat16(v.z), hw = __float2bfloat16(v.w);
    __nv_bfloat162* hp = (__nv_bfloat162*)(h + (size_t)i * 4);
    hp[0] = __nv_bfloat162(hx, hy);
    hp[1] = __nv_bfloat162(hz, hw);
    __nv_bfloat162* lp = (__nv_bfloat162*)(l + (size_t)i * 4);
    lp[0] = __nv_bfloat162(__float2bfloat16(v.x - __bfloat162float(hx)),
                           __float2bfloat16(v.y - __bfloat162float(hy)));
    lp[1] = __nv_bfloat162(__float2bfloat16(v.z - __bfloat162float(hz)),
                           __float2bfloat16(v.w - __bfloat162float(hw)));
}

// ---------------- transpose + split weights: T[n][k] = alpha*B[k][n] -------
__global__ __launch_bounds__(256) void tsplitw_k(
    const float* __restrict__ B, __nv_bfloat16* __restrict__ Th,
    __nv_bfloat16* __restrict__ Tl, int K, int N, float alpha)
{
    __shared__ float tile[32][33];
    const int tx = threadIdx.x & 31, ty = threadIdx.x >> 5;
    const int n0 = blockIdx.x * 32, k0 = blockIdx.y * 32;
#pragma unroll
    for (int i = 0; i < 32; i += 8)
        tile[ty + i][tx] = B[(size_t)(k0 + ty + i) * N + n0 + tx];
    __syncthreads();
#pragma unroll
    for (int i = 0; i < 32; i += 8) {
        float v = alpha * tile[tx][ty + i];
        __nv_bfloat16 h = __float2bfloat16(v);
        size_t o = (size_t)(n0 + ty + i) * K + k0 + tx;
        Th[o] = h;
        Tl[o] = __float2bfloat16(v - __bfloat162float(h));
    }
}

// ---------------- build combined weight [Wq*scale | Wkr | 0 | Wdkv]^T -----
__global__ __launch_bounds__(256) void buildwc_k(
    const float* __restrict__ Wq, const float* __restrict__ Wkr,
    const float* __restrict__ Wdkv, __nv_bfloat16* __restrict__ Th,
    __nv_bfloat16* __restrict__ Tl, float scale)
{
    __shared__ float tile[32][33];
    const int tx = threadIdx.x & 31, ty = threadIdx.x >> 5;
    const int n0 = blockIdx.x * 32, k0 = blockIdx.y * 32;

    const float* src; int Nsrc, nc; float alpha;
    if (n0 < 3072)      { src = Wq;   Nsrc = NQ_;  nc = n0;        alpha = scale; }
    else if (n0 < 3136) { src = Wkr;  Nsrc = DR_;  nc = n0 - 3072; alpha = 1.0f; }
    else if (n0 < 3200) { src = 0;    Nsrc = 0;    nc = 0;         alpha = 0.0f; }
    else                { src = Wdkv; Nsrc = LAT_; nc = n0 - 3200; alpha = 1.0f; }

    if (src) {
#pragma unroll
        for (int i = 0; i < 32; i += 8)
            tile[ty + i][tx] = src[(size_t)(k0 + ty + i) * Nsrc + nc + tx];
    } else {
#pragma unroll
        for (int i = 0; i < 32; i += 8)
            tile[ty + i][tx] = 0.f;
    }
    __syncthreads();
#pragma unroll
    for (int i = 0; i < 32; i += 8) {
        float v = alpha * tile[tx][ty + i];
        __nv_bfloat16 h = __float2bfloat16(v);
        size_t o = (size_t)(n0 + ty + i) * DIM_ + k0 + tx;
        Th[o] = h;
        Tl[o] = __float2bfloat16(v - __bfloat162float(h));
    }
}

// ---------------- bf16 split-2 HMMA GEMM ----------------------------------
// 128 threads, 4 warps in a 2x2 grid, warp tile 64x64: smem LDSM traffic
// drops from 96KB to 64KB per K-32 chunk (A read x2 -> x2, B read x4 -> x2).
// 3-stage cp.async pipeline, 2 CTAs/SM.
#define STG_A 8192
#define STG   32768
#define GEMM_SMEM (3 * STG)

__global__ __launch_bounds__(128, 2) void gemm_mma(
    const __nv_bfloat16* __restrict__ Ah, const __nv_bfloat16* __restrict__ Al,
    const __nv_bfloat16* __restrict__ Bh, const __nv_bfloat16* __restrict__ Bl,
    float* __restrict__ C, __nv_bfloat16* __restrict__ Ch,
    __nv_bfloat16* __restrict__ Cl, int M, int N, int K, int lda, int out_hl)
{
    extern __shared__ char smc[];
    const uint32_t sb = smem_u32(smc);
    const int t = threadIdx.x, wid = t >> 5, lane = t & 31;
    const int m0 = blockIdx.y * 128, n0 = blockIdx.x * 128;
    const int wr = (wid & 1) * 64, wc = (wid >> 1) * 64;

    float acc[4][8][4];
#pragma unroll
    for (int a = 0; a < 4; a++)
#pragma unroll
        for (int b = 0; b < 8; b++)
#pragma unroll
            for (int c = 0; c < 4; c++) acc[a][b][c] = 0.f;

    const int nk = K >> 5;

    auto load_stage = [&](int kc, int s) {
        const uint32_t base = sb + s * STG;
#pragma unroll
        for (int i = 0; i < 4; i++) {
            const int idx = t + i * 128;          // 0..511
            const int r = idx >> 2, c = idx & 3;
            const uint32_t sw = (uint32_t)(r * 64 + ((c ^ ((r >> 1) & 3)) * 16));
            const size_t ga = (size_t)(m0 + r) * lda + kc * 32 + c * 8;
            const size_t gb = (size_t)(n0 + r) * K + kc * 32 + c * 8;
            cpa16(base + sw,             Ah + ga);
            cpa16(base + STG_A + sw,     Al + ga);
            cpa16(base + 2 * STG_A + sw, Bh + gb);
            cpa16(base + 3 * STG_A + sw, Bl + gb);
        }
        cpa_commit();
    };

    // 3 stages, prefetch distance 2, one barrier per iteration.
    load_stage(0, 0);
    load_stage(1, 1);

    for (int kc = 0; kc < nk; kc++) {
        const int s = kc % 3;
        cpa_wait1();          // load(kc) resident (<=1 group pending)
        __syncthreads();      // all warps done with the stage being refilled
        if (kc + 2 < nk) load_stage(kc + 2, (kc + 2) % 3);
        else cpa_commit();    // keep group accounting aligned
        const uint32_t base = sb + s * STG;

#pragma unroll
        for (int ks = 0; ks < 2; ks++) {
            uint32_t ah[4][4], al[4][4];
#pragma unroll
            for (int mi = 0; mi < 4; mi++) {
                const int r = wr + mi * 16 + (lane & 15);
                const int ch = ks * 2 + (lane >> 4);
                const uint32_t ad = base + r * 64 + ((ch ^ ((r >> 1) & 3)) * 16);
                ldmx4(ah[mi], ad);
                ldmx4(al[mi], ad + STG_A);
            }
#pragma unroll
            for (int p = 0; p < 4; p++) {
                const int r = wc + p * 16 + (lane & 7) + ((lane >> 4) << 3);
                const int ch = ks * 2 + ((lane >> 3) & 1);
                const uint32_t bd = base + 2 * STG_A + r * 64 + ((ch ^ ((r >> 1) & 3)) * 16);
                uint32_t bh[4], bl[4];
                ldmx4(bh, bd);
                ldmx4(bl, bd + STG_A);
                // pass-major: 8 distinct accumulators between dependent MMAs
#pragma unroll
                for (int hh = 0; hh < 2; hh++)
#pragma unroll
                    for (int mi = 0; mi < 4; mi++)
                        mma16816(acc[mi][p * 2 + hh], ah[mi], bh + hh * 2);
#pragma unroll
                for (int hh = 0; hh < 2; hh++)
#pragma unroll
                    for (int mi = 0; mi < 4; mi++)
                        mma16816(acc[mi][p * 2 + hh], ah[mi], bl + hh * 2);
#pragma unroll
                for (int hh = 0; hh < 2; hh++)
#pragma unroll
                    for (int mi = 0; mi < 4; mi++)
                        mma16816(acc[mi][p * 2 + hh], al[mi], bh + hh * 2);
            }
        }
    }

    // epilogue (C row stride == N)
#pragma unroll
    for (int mi = 0; mi < 4; mi++) {
#pragma unroll
        for (int ni = 0; ni < 8; ni++) {
            const int r0 = m0 + wr + mi * 16 + (lane >> 2);
            const int c0 = n0 + wc + ni * 8 + (lane & 3) * 2;
            if (out_hl) {
#pragma unroll
                for (int half = 0; half < 2; half++) {
                    const size_t o = (size_t)(r0 + half * 8) * N + c0;
                    const float v0 = acc[mi][ni][half * 2 + 0];
                    const float v1 = acc[mi][ni][half * 2 + 1];
                    __nv_bfloat162 hv = __floats2bfloat162_rn(v0, v1);
                    *(__nv_bfloat162*)(Ch + o) = hv;
                    *(__nv_bfloat162*)(Cl + o) = __floats2bfloat162_rn(
                        v0 - __bfloat162float(hv.x), v1 - __bfloat162float(hv.y));
                }
            } else {
                float2 v0, v1;
                v0.x = acc[mi][ni][0]; v0.y = acc[mi][ni][1];
                v1.x = acc[mi][ni][2]; v1.y = acc[mi][ni][3];
                *(float2*)&C[(size_t)r0 * N + c0]       = v0;
                *(float2*)&C[(size_t)(r0 + 8) * N + c0] = v1;
            }
        }
    }
}

// ---------------- RoPE in hi/lo domain (q rope blocks + kr block) ---------
__global__ void rope_hl(__nv_bfloat16* __restrict__ h, __nv_bfloat16* __restrict__ l)
{
    int idx = blockIdx.x * blockDim.x + threadIdx.x;   // ROWS*17*32
    if (idx >= ROWS * 17 * 32) return;
    int i   = idx & 31;
    int u   = (idx >> 5) % 17;
    int row = (idx >> 5) / 17;
    int pos = row & (SS - 1);
    float inv = powf(10000.0f, -(float)i / 32.0f);
    float ang = (float)pos * inv;
    float s, c; sincosf(ang, &s, &c);
    size_t base = (size_t)row * CS_ + (u < 16 ? u * 192 + 128 : 3072);
    float x1 = __bfloat162float(h[base + i])      + __bfloat162float(l[base + i]);
    float x2 = __bfloat162float(h[base + i + 32]) + __bfloat162float(l[base + i + 32]);
    float r1 = x1 * c - x2 * s;
    float r2 = x2 * c + x1 * s;
    __nv_bfloat16 h1 = __float2bfloat16(r1), h2 = __float2bfloat16(r2);
    h[base + i]      = h1;
    l[base + i]      = __float2bfloat16(r1 - __bfloat162float(h1));
    h[base + i + 32] = h2;
    l[base + i + 32] = __float2bfloat16(r2 - __bfloat162float(h2));
}

// ---------------- flash attention, split-2 bf16 HMMA, overlapped loads ----
#define ASTR_ 384
#define VSTR_ 256
#define OQH 0
#define OQL 49152
#define OKH 98304
#define OKL 122880
#define OVH 147456
#define OVL 163840
#define ATT_SMEM 180224

__global__ __launch_bounds__(256, 1) void attn_mma(
    const __nv_bfloat16* __restrict__ qh,  const __nv_bfloat16* __restrict__ ql,
    const __nv_bfloat16* __restrict__ kvh, const __nv_bfloat16* __restrict__ kvl,
    __nv_bfloat16* __restrict__ atth, __nv_bfloat16* __restrict__ attl)
{
    extern __shared__ char smc[];
    const uint32_t sb = smem_u32(smc);
    const int t = threadIdx.x, w = t >> 5, lane = t & 31;
    const int qt = gridDim.x - 1 - blockIdx.x;   // heavy tiles first
    const int h = blockIdx.y, b = blockIdx.z;
    const int q0 = qt * 128;
    const int rowg0 = b * SS + q0;
    const int g = lane >> 2, tq = lane & 3;
    const int qr0 = q0 + w * 16 + g;

    auto loadK = [&](int kt) {
        const int k0 = kt * 64;
#pragma unroll
        for (int it = 0; it < 6; it++) {
            const int idx = t + it * 256;        // 64*24
            const int r = idx / 24, c = idx % 24;
            const uint32_t dst = sb + r * ASTR_ + ((c ^ (r & 7)) * 16);
            const size_t rg = (size_t)(b * SS + k0 + r);
            if (c < 16) {
                const size_t go = rg * NKV_ + h * 256 + c * 8;
                cpa16(dst + OKH, kvh + go);
                cpa16(dst + OKL, kvl + go);
            } else {
                const size_t go = rg * CS_ + 3072 + (c - 16) * 8;
                cpa16(dst + OKH, qh + go);
                cpa16(dst + OKL, ql + go);
            }
        }
        cpa_commit();
    };
    auto loadV = [&](int kt) {
        const int k0 = kt * 64;
#pragma unroll
        for (int it = 0; it < 4; it++) {
            const int idx = t + it * 256;        // 64*16
            const int r = idx >> 4, c = idx & 15;
            const uint32_t dst = sb + r * VSTR_ + ((c ^ (r & 7)) * 16);
            const size_t go = (size_t)(b * SS + k0 + r) * NKV_ + h * 256 + 128 + c * 8;
            cpa16(dst + OVH, kvh + go);
            cpa16(dst + OVL, kvl + go);
        }
        cpa_commit();
    };

    // ---- prologue: Q tile + K(0) ----
#pragma unroll
    for (int it = 0; it < 12; it++) {
        const int idx = t + it * 256;            // 128*24
        const int r = idx / 24, c = idx % 24;
        const uint32_t dst = sb + r * ASTR_ + ((c ^ (r & 7)) * 16);
        const size_t go = (size_t)(rowg0 + r) * CS_ + h * 192 + c * 8;
        cpa16(dst + OQH, qh + go);
        cpa16(dst + OQL, ql + go);
    }
    cpa_commit();
    loadK(0);

    float m0 = -1e30f, m1 = -1e30f, l0 = 0.f, l1 = 0.f;
    float oacc[16][4];
#pragma unroll
    for (int i = 0; i < 16; i++)
#pragma unroll
        for (int j = 0; j < 4; j++) oacc[i][j] = 0.f;

    const int nkt = 2 * qt + 2;
    const int wkmax = q0 + w * 16 + 15;

    for (int kt = 0; kt < nkt; kt++) {
        const int k0 = kt * 64;
        cpa_wait0();          // K(kt) (and Q on first iter) resident
        __syncthreads();      // prior PV done -> V buffer free
        loadV(kt);            // V(kt) overlaps QK compute

        const bool active = (k0 <= wkmax);
        float sacc[8][4];
        if (active) {
#pragma unroll
            for (int p = 0; p < 8; p++)
#pragma unroll
                for (int c = 0; c < 4; c++) sacc[p][c] = 0.f;

            for (int kc = 0; kc < 12; kc++) {
                const int ra = w * 16 + (lane & 15);
                const int ca = kc * 2 + (lane >> 4);
                const uint32_t qa = sb + ra * ASTR_ + ((ca ^ (ra & 7)) * 16);
                uint32_t aQh[4], aQl[4];
                ldmx4(aQh, qa + OQH);
                ldmx4(aQl, qa + OQL);
#pragma unroll
                for (int g16 = 0; g16 < 4; g16++) {
                    const int rb = g16 * 16 + (lane & 7) + ((lane >> 4) << 3);
                    const int cb = kc * 2 + ((lane >> 3) & 1);
                    const uint32_t ka = sb + rb * ASTR_ + ((cb ^ (rb & 7)) * 16);
                    uint32_t bKh[4], bKl[4];
                    ldmx4(bKh, ka + OKH);
                    ldmx4(bKl, ka + OKL);
#pragma unroll
                    for (int hh = 0; hh < 2; hh++)
                        mma16816(sacc[g16 * 2 + hh], aQh, bKh + hh * 2);
#pragma unroll
                    for (int hh = 0; hh < 2; hh++)
                        mma16816(sacc[g16 * 2 + hh], aQh, bKl + hh * 2);
#pragma unroll
                    for (int hh = 0; hh < 2; hh++)
                        mma16816(sacc[g16 * 2 + hh], aQl, bKh + hh * 2);
                }
            }
        }

        cpa_wait0();          // V(kt) resident
        __syncthreads();      // all warps done with K(kt)
        if (kt + 1 < nkt) loadK(kt + 1);   // overlaps softmax + PV

        if (active) {
            if (k0 + 63 > q0 + w * 16) {
#pragma unroll
                for (int p = 0; p < 8; p++) {
                    const int colb = k0 + p * 8 + 2 * tq;
#pragma unroll
                    for (int c = 0; c < 4; c++) {
                        const int col = colb + (c & 1);
                        const int row = qr0 + ((c >> 1) << 3);
                        if (col > row) sacc[p][c] = -1e30f;
                    }
                }
            }

            float t0 = -1e30f, t1 = -1e30f;
#pragma unroll
            for (int p = 0; p < 8; p++) {
                t0 = fmaxf(t0, fmaxf(sacc[p][0], sacc[p][1]));
                t1 = fmaxf(t1, fmaxf(sacc[p][2], sacc[p][3]));
            }
            t0 = fmaxf(t0, __shfl_xor_sync(0xffffffffu, t0, 1));
            t0 = fmaxf(t0, __shfl_xor_sync(0xffffffffu, t0, 2));
            t1 = fmaxf(t1, __shfl_xor_sync(0xffffffffu, t1, 1));
            t1 = fmaxf(t1, __shfl_xor_sync(0xffffffffu, t1, 2));
            const float mn0 = fmaxf(m0, t0), mn1 = fmaxf(m1, t1);
            const float a0 = __expf(m0 - mn0), a1 = __expf(m1 - mn1);
            m0 = mn0; m1 = mn1;
            float s0 = 0.f, s1 = 0.f;
#pragma unroll
            for (int p = 0; p < 8; p++) {
                sacc[p][0] = __expf(sacc[p][0] - m0); s0 += sacc[p][0];
                sacc[p][1] = __expf(sacc[p][1] - m0); s0 += sacc[p][1];
                sacc[p][2] = __expf(sacc[p][2] - m1); s1 += sacc[p][2];
                sacc[p][3] = __expf(sacc[p][3] - m1); s1 += sacc[p][3];
            }
            s0 += __shfl_xor_sync(0xffffffffu, s0, 1);
            s0 += __shfl_xor_sync(0xffffffffu, s0, 2);
            s1 += __shfl_xor_sync(0xffffffffu, s1, 1);
            s1 += __shfl_xor_sync(0xffffffffu, s1, 2);
            l0 = l0 * a0 + s0;
            l1 = l1 * a1 + s1;

#pragma unroll
            for (int nt = 0; nt < 16; nt++) {
                oacc[nt][0] *= a0; oacc[nt][1] *= a0;
                oacc[nt][2] *= a1; oacc[nt][3] *= a1;
            }

#pragma unroll
            for (int kc2 = 0; kc2 < 4; kc2++) {
                uint32_t aPh[4], aPl[4];
#pragma unroll
                for (int u = 0; u < 4; u++) {
                    const float* pp = &sacc[kc2 * 2 + (u >> 1)][(u & 1) * 2];
                    const float p0 = pp[0], p1 = pp[1];
                    __nv_bfloat162 hv = __floats2bfloat162_rn(p0, p1);
                    aPh[u] = *(uint32_t*)&hv;
                    __nv_bfloat162 lv = __floats2bfloat162_rn(
                        p0 - __bfloat162float(hv.x), p1 - __bfloat162float(hv.y));
                    aPl[u] = *(uint32_t*)&lv;
                }
#pragma unroll
                for (int v16 = 0; v16 < 8; v16++) {
                    const int rv = kc2 * 16 + (lane & 7) + (((lane >> 3) & 1) << 3);
                    const int cv = v16 * 2 + (lane >> 4);
                    const uint32_t va = sb + rv * VSTR_ + ((cv ^ (rv & 7)) * 16);
                    uint32_t bVh[4], bVl[4];
                    ldmx4t(bVh, va + OVH);
                    ldmx4t(bVl, va + OVL);
#pragma unroll
                    for (int hh = 0; hh < 2; hh++)
                        mma16816(oacc[v16 * 2 + hh], aPh, bVh + hh * 2);
#pragma unroll
                    for (int hh = 0; hh < 2; hh++)
                        mma16816(oacc[v16 * 2 + hh], aPh, bVl + hh * 2);
#pragma unroll
                    for (int hh = 0; hh < 2; hh++)
                        mma16816(oacc[v16 * 2 + hh], aPl, bVh + hh * 2);
                }
            }
        }
    }

    // ---- epilogue ----
    const float i0 = 1.0f / l0, i1 = 1.0f / l1;
#pragma unroll
    for (int nt = 0; nt < 16; nt++) {
        const size_t base0 = (size_t)(rowg0 + w * 16 + g) * NO_ + h * 128 + nt * 8 + 2 * tq;
        const size_t base1 = base0 + (size_t)8 * NO_;
        float o0 = oacc[nt][0] * i0, o1 = oacc[nt][1] * i0;
        __nv_bfloat162 hv = __floats2bfloat162_rn(o0, o1);
        *(__nv_bfloat162*)(atth + base0) = hv;
        *(__nv_bfloat162*)(attl + base0) = __floats2bfloat162_rn(
            o0 - __bfloat162float(hv.x), o1 - __bfloat162float(hv.y));
        float o2 = oacc[nt][2] * i1, o3 = oacc[nt][3] * i1;
        __nv_bfloat162 hv2 = __floats2bfloat162_rn(o2, o3);
        *(__nv_bfloat162*)(atth + base1) = hv2;
        *(__nv_bfloat162*)(attl + base1) = __floats2bfloat162_rn(
            o2 - __bfloat162float(hv2.x), o3 - __bfloat162float(hv2.y));
    }
}

// ---------------- launch ----------------
extern "C" void kernel_launch(void* const* d_in, const int* in_sizes, int n_in,
                              void* d_out, int out_size)
{
    const float* x    = (const float*)d_in[0];
    const float* Wq   = (const float*)d_in[1];
    const float* Wdkv = (const float*)d_in[2];
    const float* Wkr  = (const float*)d_in[3];
    const float* Wukv = (const float*)d_in[4];
    const float* Wo   = (const float*)d_in[5];
    float* out = (float*)d_out;

    __nv_bfloat16 *xh, *xl, *ph, *pl, *kvh, *kvl, *atth, *attl;
    __nv_bfloat16 *wch, *wcl, *wuh, *wul, *woh, *wol;
    cudaGetSymbolAddress((void**)&xh,   g_xh);
    cudaGetSymbolAddress((void**)&xl,   g_xl);
    cudaGetSymbolAddress((void**)&ph,   g_ph);
    cudaGetSymbolAddress((void**)&pl,   g_pl);
    cudaGetSymbolAddress((void**)&kvh,  g_kvh);
    cudaGetSymbolAddress((void**)&kvl,  g_kvl);
    cudaGetSymbolAddress((void**)&atth, g_atth);
    cudaGetSymbolAddress((void**)&attl, g_attl);
    cudaGetSymbolAddress((void**)&wch,  g_wch);
    cudaGetSymbolAddress((void**)&wcl,  g_wcl);
    cudaGetSymbolAddress((void**)&wuh,  g_wuh);
    cudaGetSymbolAddress((void**)&wul,  g_wul);
    cudaGetSymbolAddress((void**)&woh,  g_woh);
    cudaGetSymbolAddress((void**)&wol,  g_wol);

    const float scale = 1.0f / sqrtf((float)(DH_ + DR_));
    dim3 blk(256);
    dim3 gblk(128);

    cudaFuncSetAttribute(gemm_mma, cudaFuncAttributeMaxDynamicSharedMemorySize, GEMM_SMEM);
    cudaFuncSetAttribute(attn_mma, cudaFuncAttributeMaxDynamicSharedMemorySize, ATT_SMEM);

    // 0: combined weight  [Wq*scale | Wkr | 0 | Wdkv]^T
    buildwc_k<<<dim3(CS_ / 32, DIM_ / 32), blk>>>(Wq, Wkr, Wdkv, wch, wcl, scale);
    // 1: x split
    split_k<<<ROWS * DIM_ / 4 / 256, blk>>>(x, xh, xl, ROWS * DIM_ / 4);
    // 2: Wukv transpose/split
    tsplitw_k<<<dim3(NKV_ / 32, LAT_ / 32), blk>>>(Wukv, wuh, wul, LAT_, NKV_, 1.0f);
    // 3 (ncu capture index): [q | kr | pad | ckv] = x @ Wc  -> hi/lo
    gemm_mma<<<dim3(CS_ / 128, ROWS / 128), gblk, GEMM_SMEM>>>(
        xh, xl, wch, wcl, nullptr, ph, pl, ROWS, CS_, DIM_, DIM_, 1);
    // 4: Wo transpose/split
    tsplitw_k<<<dim3(DIM_ / 32, NO_ / 32), blk>>>(Wo, woh, wol, NO_, DIM_, 1.0f);
    // 5: kv = ckv @ Wukv  (ckv in place from combined buffer, lda=CS_)
    gemm_mma<<<dim3(NKV_ / 128, ROWS / 128), gblk, GEMM_SMEM>>>(
        ph + 3200, pl + 3200, wuh, wul, nullptr, kvh, kvl, ROWS, NKV_, LAT_, CS_, 1);
    // 6: RoPE in hi/lo domain
    rope_hl<<<(ROWS * 17 * 32 + 255) / 256, blk>>>(ph, pl);
    // 7: attention
    attn_mma<<<dim3(SS / 128, HH, BB), blk, ATT_SMEM>>>(ph, pl, kvh, kvl, atth, attl);
    // 8: out = att @ Wo  -> fp32
    gemm_mma<<<dim3(DIM_ / 128, ROWS / 128), gblk, GEMM_SMEM>>>(
        atth, attl, woh, wol, out, nullptr, nullptr, ROWS, DIM_, NO_, NO_, 0);
}